// round 15
// baseline (speedup 1.0000x reference)
#include <cuda_runtime.h>
#include <cuda_fp16.h>
#include <math.h>
#include <stdint.h>

#define B_ 2
#define T_ 2048
#define D_ 1024
#define H_ 16
#define DH_ 64
#define SCALE_ 0.03125f     /* 1/sqrt(1024) exactly */

#define ASTRIDE ((size_t)4096*1024)
#define WSTRIDE ((size_t)1024*1024)

// ============================================================================
// Scratch (static device globals — no allocation in kernel_launch)
// g_Ah slab 0 doubles as the fp16 context buffer (attention epilogue output).
// ============================================================================
__device__ __half g_Ah[3*ASTRIDE];
__device__ __half g_Wh[4*WSTRIDE];
__device__ __half g_Qh[(size_t)B_*H_*T_*DH_];
__device__ __half g_Kh[(size_t)B_*H_*T_*DH_];   // compacted
__device__ __half g_Vh[(size_t)B_*H_*T_*DH_];   // compacted
__device__ int g_pos[B_*T_];
__device__ int g_cnt[B_];

// ============================================================================
// mma.sync / ldmatrix / cp.async helpers (base-target PTX)
// ============================================================================
__device__ __forceinline__ unsigned smem_u32(const void* p) {
    unsigned a;
    asm("{ .reg .u64 t; cvta.to.shared.u64 t, %1; cvt.u32.u64 %0, t; }"
        : "=r"(a) : "l"(p));
    return a;
}
__device__ __forceinline__ void mma_fp(float* c, const unsigned* a, const unsigned* b) {
    asm volatile(
        "mma.sync.aligned.m16n8k16.row.col.f32.f16.f16.f32 "
        "{%0,%1,%2,%3}, {%4,%5,%6,%7}, {%8,%9}, {%0,%1,%2,%3};"
        : "+f"(c[0]), "+f"(c[1]), "+f"(c[2]), "+f"(c[3])
        : "r"(a[0]), "r"(a[1]), "r"(a[2]), "r"(a[3]), "r"(b[0]), "r"(b[1]));
}
__device__ __forceinline__ void ldsm4(unsigned* r, unsigned a) {
    asm volatile("ldmatrix.sync.aligned.m8n8.x4.shared.b16 {%0,%1,%2,%3}, [%4];"
        : "=r"(r[0]), "=r"(r[1]), "=r"(r[2]), "=r"(r[3]) : "r"(a));
}
__device__ __forceinline__ void ldsm4t(unsigned* r, unsigned a) {
    asm volatile("ldmatrix.sync.aligned.m8n8.x4.trans.shared.b16 {%0,%1,%2,%3}, [%4];"
        : "=r"(r[0]), "=r"(r[1]), "=r"(r[2]), "=r"(r[3]) : "r"(a));
}
#define CP16(dst_u32, src_ptr) \
    asm volatile("cp.async.cg.shared.global [%0], [%1], 16;" \
        :: "r"(dst_u32), "l"(src_ptr) : "memory")
#define CP_COMMIT() asm volatile("cp.async.commit_group;" ::: "memory")
#define CP_WAIT1()  asm volatile("cp.async.wait_group 1;"  ::: "memory")

// ============================================================================
// prep: fused conversions + mask scan, MLP=4 per thread.
//   blocks [0, 3072):    A conv (q,k,v), 1024 blocks each, 4 float4/thread
//   blocks [3072, 4096): W conv (4 weights), 256 blocks each
//   blocks [4096, 4098): per-batch mask prefix scan
// ============================================================================
__global__ void __launch_bounds__(256) prep(
    const float* __restrict__ q, const float* __restrict__ k,
    const float* __restrict__ v,
    const float* __restrict__ wq, const float* __restrict__ wk,
    const float* __restrict__ wv, const float* __restrict__ wo,
    const int* __restrict__ mask,
    __half* __restrict__ AhB, __half* __restrict__ WhB)
{
    const int bid = blockIdx.x, tid = threadIdx.x;
    if (bid < 4096) {
        const float* src;
        __half* dst;
        int i0;
        if (bid < 3072) {
            const int z = bid >> 10;
            src = (z == 0) ? q : (z == 1) ? k : v;
            dst = AhB + (size_t)z*ASTRIDE;
            i0 = (bid & 1023) * 1024 + tid;
        } else {
            const int zb = bid - 3072;
            const int z = zb >> 8;
            src = (z == 0) ? wq : (z == 1) ? wk : (z == 2) ? wv : wo;
            dst = WhB + (size_t)z*WSTRIDE;
            i0 = (zb & 255) * 1024 + tid;
        }
        float4 w[4];
        #pragma unroll
        for (int j = 0; j < 4; j++) w[j] = ((const float4*)src)[i0 + j*256];
        #pragma unroll
        for (int j = 0; j < 4; j++) {
            int i = i0 + j*256;
            __half2 a; a.x = __float2half_rn(w[j].x); a.y = __float2half_rn(w[j].y);
            __half2 b; b.x = __float2half_rn(w[j].z); b.y = __float2half_rn(w[j].w);
            ((__half2*)dst)[2*i]   = a;
            ((__half2*)dst)[2*i+1] = b;
        }
    } else {
        __shared__ int ps[256];
        const int b = bid - 4096;
        const int base = b*T_ + tid*8;
        int a[8], s = 0;
        #pragma unroll
        for (int j = 0; j < 8; j++) { a[j] = (mask[base + j] != 0); s += a[j]; }
        ps[tid] = s;
        __syncthreads();
        for (int off = 1; off < 256; off <<= 1) {
            int vsum = ps[tid] + ((tid >= off) ? ps[tid - off] : 0);
            __syncthreads();
            ps[tid] = vsum;
            __syncthreads();
        }
        int run = (tid > 0) ? ps[tid-1] : 0;
        #pragma unroll
        for (int j = 0; j < 8; j++) {
            g_pos[base + j] = a[j] ? run : -1;
            run += a[j];
        }
        if (tid == 255) g_cnt[b] = ps[255];
    }
}

// ============================================================================
// GEMM core: Y = Ah @ Wh + bias   (fp16 single-stream) — unchanged from R13
// ============================================================================
#define GST 35840
#define G_WH_OFF 18432
#define GEMM_SMEM (3*GST)

__device__ __forceinline__ void gemm_core(
    char* gsm,
    const __half* __restrict__ Ah, const __half* __restrict__ Wh,
    const float* __restrict__ bias,
    float* __restrict__ Yf, __half* __restrict__ Yh,
    int emode, int m0, int n0)
{
    const int tid = threadIdx.x, lane = tid & 31, wid = tid >> 5;
    const int wm = wid >> 2, wn = wid & 3;

    float c[4][4][4];
    #pragma unroll
    for (int i = 0; i < 4; i++)
        #pragma unroll
        for (int j = 0; j < 4; j++)
            #pragma unroll
            for (int e = 0; e < 4; e++) c[i][j][e] = 0.f;

    const int l15 = lane & 15, lh8 = (lane >> 4) << 3;
    const unsigned smb = smem_u32(gsm);

    int a_row[4], a_c8[4], w_row[4], w_c8[4];
    #pragma unroll
    for (int t = 0; t < 4; t++) {
        int ch = tid + t*256;
        a_row[t] = ch >> 3;  a_c8[t] = (ch & 7) << 3;
        w_row[t] = ch >> 4;  w_c8[t] = (ch & 15) << 3;
    }

    auto issue = [&](int s, int k0) {
        const unsigned base = smb + s*GST;
        #pragma unroll
        for (int t = 0; t < 4; t++) {
            unsigned aso = base + (unsigned)(a_row[t]*144 + a_c8[t]*2);
            size_t ago = (size_t)(m0 + a_row[t])*1024 + k0 + a_c8[t];
            CP16(aso, Ah + ago);
            unsigned wso = base + G_WH_OFF + (unsigned)(w_row[t]*272 + w_c8[t]*2);
            size_t wgo = (size_t)(k0 + w_row[t])*1024 + n0 + w_c8[t];
            CP16(wso, Wh + wgo);
        }
    };

    issue(0, 0);
    CP_COMMIT();
    issue(1, 64);
    CP_COMMIT();

    for (int kc = 0; kc < 16; kc++) {
        CP_WAIT1();
        __syncthreads();
        if (kc + 2 < 16) issue((kc + 2) % 3, (kc + 2) << 6);
        CP_COMMIT();

        const int buf = kc % 3;
        const __half* sAh = (const __half*)(gsm + buf*GST);
        const __half* sWh = (const __half*)(gsm + buf*GST + G_WH_OFF);

        #pragma unroll
        for (int kk = 0; kk < 64; kk += 16) {
            unsigned a[4][4], bh_[4][2], t4[4];
            #pragma unroll
            for (int mi = 0; mi < 4; mi++)
                ldsm4(a[mi], smem_u32(&sAh[(wm*64 + mi*16 + l15)*72 + kk + lh8]));
            #pragma unroll
            for (int p = 0; p < 2; p++) {
                ldsm4t(t4, smem_u32(&sWh[(kk + l15)*136 + wn*32 + p*16 + lh8]));
                bh_[2*p][0]=t4[0]; bh_[2*p][1]=t4[1];
                bh_[2*p+1][0]=t4[2]; bh_[2*p+1][1]=t4[3];
            }
            #pragma unroll
            for (int mi = 0; mi < 4; mi++)
                #pragma unroll
                for (int ni = 0; ni < 4; ni++) mma_fp(c[mi][ni], a[mi], bh_[ni]);
        }
    }

    // Epilogue
    const int rA = lane >> 2, c2 = (lane & 3) << 1;
    #pragma unroll
    for (int mi = 0; mi < 4; mi++) {
        const int rowA = m0 + wm*64 + mi*16 + rA;
        const int rowB = rowA + 8;
        int pA = rowA & (T_-1), pB = rowB & (T_-1);
        if (emode == 1) { pA = g_pos[rowA]; pB = g_pos[rowB]; }
        #pragma unroll
        for (int ni = 0; ni < 4; ni++) {
            const int col = n0 + wn*32 + ni*8 + c2;
            float2 bb = *(const float2*)(bias + col);
            float v00 = c[mi][ni][0] + bb.x, v01 = c[mi][ni][1] + bb.y;
            float v10 = c[mi][ni][2] + bb.x, v11 = c[mi][ni][3] + bb.y;
            if (emode == 2) {
                float2 w0; w0.x = v00; w0.y = v01;
                float2 w1; w1.x = v10; w1.y = v11;
                *(float2*)(Yf + (size_t)rowA * 1024 + col) = w0;
                *(float2*)(Yf + (size_t)rowB * 1024 + col) = w1;
            } else {
                const int hh = col >> 6, dd = col & 63;
                const int bA = rowA >> 11, bB = rowB >> 11;
                __half2 ph0; ph0.x = __float2half_rn(v00); ph0.y = __float2half_rn(v01);
                __half2 ph1; ph1.x = __float2half_rn(v10); ph1.y = __float2half_rn(v11);
                if (pA >= 0) {
                    size_t oA = (((size_t)(bA*H_ + hh))*T_ + pA)*64 + dd;
                    *(__half2*)(Yh + oA) = ph0;
                }
                if (pB >= 0) {
                    size_t oB = (((size_t)(bB*H_ + hh))*T_ + pB)*64 + dd;
                    *(__half2*)(Yh + oB) = ph1;
                }
            }
        }
    }
}

__global__ void __launch_bounds__(256, 2) gemm_qkv(
    const __half* __restrict__ AhB, const __half* __restrict__ WhB,
    const float* __restrict__ bq, const float* __restrict__ bk,
    const float* __restrict__ bv,
    __half* __restrict__ Qh, __half* __restrict__ Kh, __half* __restrict__ Vh)
{
    extern __shared__ __align__(16) char gsm[];
    const int z = blockIdx.z;
    const float* bias = (z == 0) ? bq : (z == 1) ? bk : bv;
    __half* Yh = (z == 0) ? Qh : (z == 1) ? Kh : Vh;
    gemm_core(gsm, AhB + z*ASTRIDE, WhB + z*WSTRIDE, bias,
              nullptr, Yh, (z == 0) ? 0 : 1,
              blockIdx.y << 7, blockIdx.x << 7);
}

__global__ void __launch_bounds__(256, 2) gemm_out(
    const __half* __restrict__ AhB, const __half* __restrict__ WhB,
    const float* __restrict__ bo, float* __restrict__ out)
{
    extern __shared__ __align__(16) char gsm[];
    gemm_core(gsm, AhB, WhB + 3*WSTRIDE, bo,
              out, nullptr, 2, blockIdx.y << 7, blockIdx.x << 7);
}

// ============================================================================
// Flash attention, warp-per-row-group, K-tile = 128 keys (two 64-key halves
// sharing the warp-private P buffer). S = Qh·Kh; PV = Ph·Vh.
// ============================================================================
#define ATT_QH   0          /* 128 x 72 half = 18432 */
#define ATT_K    18432      /* 2 bufs x (128 x 72 half) = 36864 */
#define ATT_V    55296      /* 2 bufs x (128 x 72 half) = 36864 */
#define ATT_PH   92160      /* 128 x 72 half = 18432 (64-key half) */
#define ATT_SMEM 110592

__global__ void __launch_bounds__(256, 2) attn_mma()
{
    extern __shared__ __align__(16) char sm[];
    __half* sQh = (__half*)(sm + ATT_QH);
    __half* sPh = (__half*)(sm + ATT_PH);

    const int tid = threadIdx.x, lane = tid & 31, wid = tid >> 5;
    const int qt0 = blockIdx.x << 7;
    const int hh = blockIdx.y, bb = blockIdx.z;
    const size_t base = ((size_t)(bb*H_ + hh)) * T_ * DH_;
    const int nv = g_cnt[bb];
    const int nt = (nv + 127) >> 7;

    const int r = tid >> 1, cofs = (tid & 1) << 5;
    const int l15 = lane & 15, lh8 = (lane >> 4) << 3;
    const int bn  = (lane & 7) + ((lane >> 4) << 3), bk8 = ((lane >> 3) & 1) << 3;
    const int rA0 = lane >> 2, c2 = (lane & 3) << 1;

    const unsigned smK = smem_u32(sm + ATT_K);
    const unsigned smV = smem_u32(sm + ATT_V);

    // 4 chunks/thread per 128x72-half matrix (1024 x 16B chunks)
    int ld_row[4], ld_c8[4];
    #pragma unroll
    for (int t = 0; t < 4; t++) {
        int ch = tid + t*256;
        ld_row[t] = ch >> 3;
        ld_c8[t]  = (ch & 7) << 3;
    }

    // Load Q (persistent)
    {
        const uint4* s1 = (const uint4*)(g_Qh + base + (size_t)(qt0 + r)*64 + cofs);
        uint4* d1 = (uint4*)(sQh + r*72 + cofs);
        d1[0]=s1[0]; d1[1]=s1[1]; d1[2]=s1[2]; d1[3]=s1[3];
    }

    float lrunA = 0.f, lrunB = 0.f;
    float o[8][4];
    #pragma unroll
    for (int g = 0; g < 8; g++)
        #pragma unroll
        for (int e = 0; e < 4; e++) o[g][e] = 0.f;

    // Prologue: tile 0 -> buf 0
    #pragma unroll
    for (int t = 0; t < 4; t++) {
        unsigned so = (unsigned)((ld_row[t]*72 + ld_c8[t]) * 2);
        size_t go = base + (size_t)ld_row[t]*64 + ld_c8[t];
        CP16(smK + so, g_Kh + go);
        CP16(smV + so, g_Vh + go);
    }
    CP_COMMIT();

    const int prow = wid*16;   // this warp's q-row block

    for (int kt = 0; kt < nt; kt++) {
        const int buf = kt & 1;
        if (kt + 1 < nt) {
            const size_t gofs = base + ((size_t)(kt+1) << 7) * 64;
            const unsigned kb = smK + (buf ^ 1) * 18432u;
            const unsigned vb = smV + (buf ^ 1) * 18432u;
            #pragma unroll
            for (int t = 0; t < 4; t++) {
                unsigned so = (unsigned)((ld_row[t]*72 + ld_c8[t]) * 2);
                size_t go = gofs + (size_t)ld_row[t]*64 + ld_c8[t];
                CP16(kb + so, g_Kh + go);
                CP16(vb + so, g_Vh + go);
            }
        }
        CP_COMMIT();
        CP_WAIT1();
        __syncthreads();   // (A) current K/V 128-key buffer ready

        __half* sKh = (__half*)(sm + ATT_K + buf*18432);
        __half* sVh = (__half*)(sm + ATT_V + buf*18432);

        #pragma unroll
        for (int half = 0; half < 2; half++) {
            const int kb64 = half << 6;
            // ---- S = Qh·Kh : warp computes 16 rows x 64 keys ----
            float s[8][4];
            #pragma unroll
            for (int g = 0; g < 8; g++)
                #pragma unroll
                for (int e = 0; e < 4; e++) s[g][e] = 0.f;

            #pragma unroll
            for (int kk = 0; kk < 64; kk += 16) {
                unsigned a[4], bf[8][2], t4[4];
                ldsm4(a, smem_u32(&sQh[(prow + l15)*72 + kk + lh8]));
                #pragma unroll
                for (int g = 0; g < 4; g++) {
                    ldsm4(t4, smem_u32(&sKh[(kb64 + g*16 + bn)*72 + kk + bk8]));
                    bf[2*g][0]=t4[0]; bf[2*g][1]=t4[1];
                    bf[2*g+1][0]=t4[2]; bf[2*g+1][1]=t4[3];
                }
                #pragma unroll
                for (int G = 0; G < 8; G++) mma_fp(s[G], a, bf[G]);
            }

            // ---- warp-local softmax ----
            const int k0g = (kt << 7) + kb64;
            float sumA = 0.f, sumB = 0.f;
            #pragma unroll
            for (int G = 0; G < 8; G++) {
                const int col = G*8 + c2;
                const bool v0 = (k0g + col)     < nv;
                const bool v1 = (k0g + col + 1) < nv;
                float p00 = v0 ? __expf(s[G][0]*SCALE_) : 0.f;
                float p01 = v1 ? __expf(s[G][1]*SCALE_) : 0.f;
                float p10 = v0 ? __expf(s[G][2]*SCALE_) : 0.f;
                float p11 = v1 ? __expf(s[G][3]*SCALE_) : 0.f;
                sumA += p00 + p01;  sumB += p10 + p11;
                __half2 vh0; vh0.x = __float2half_rn(p00); vh0.y = __float2half_rn(p01);
                __half2 vh1; vh1.x = __float2half_rn(p10); vh1.y = __float2half_rn(p11);
                *(__half2*)(sPh + (prow + rA0)*72 + col)     = vh0;
                *(__half2*)(sPh + (prow + rA0 + 8)*72 + col) = vh1;
            }
            sumA += __shfl_xor_sync(0xffffffffu, sumA, 1);
            sumA += __shfl_xor_sync(0xffffffffu, sumA, 2);
            sumB += __shfl_xor_sync(0xffffffffu, sumB, 1);
            sumB += __shfl_xor_sync(0xffffffffu, sumB, 2);
            lrunA += sumA;
            lrunB += sumB;
            __syncwarp();   // P visible across lanes for ldmatrix

            // ---- O += Ph·Vh : warp computes 16 rows x 64 dh ----
            #pragma unroll
            for (int kk = 0; kk < 64; kk += 16) {
                unsigned pa[4], vf[8][2], t4[4];
                ldsm4(pa, smem_u32(&sPh[(prow + l15)*72 + kk + lh8]));
                #pragma unroll
                for (int g = 0; g < 4; g++) {
                    ldsm4t(t4, smem_u32(&sVh[(kb64 + kk + l15)*72 + g*16 + lh8]));
                    vf[2*g][0]=t4[0]; vf[2*g][1]=t4[1];
                    vf[2*g+1][0]=t4[2]; vf[2*g+1][1]=t4[3];
                }
                #pragma unroll
                for (int G = 0; G < 8; G++) mma_fp(o[G], pa, vf[G]);
            }
            __syncwarp();   // P reads done before next half overwrites it
        }
        __syncthreads();   // (C) all warps done with buf before refill
    }

    // ---- normalize + write fp16 ctx into g_Ah slab 0 ----
    const float invA = 1.f / lrunA, invB = 1.f / lrunB;
    const size_t rowA = (size_t)(bb*T_ + qt0 + prow + rA0) * D_ + hh*64;
    const size_t rowB = rowA + (size_t)8 * D_;
    #pragma unroll
    for (int G = 0; G < 8; G++) {
        const int col = G*8 + c2;
        __half2 w0; w0.x = __float2half_rn(o[G][0]*invA);
        w0.y = __float2half_rn(o[G][1]*invA);
        __half2 w1; w1.x = __float2half_rn(o[G][2]*invB);
        w1.y = __float2half_rn(o[G][3]*invB);
        *(__half2*)(g_Ah + rowA + col) = w0;
        *(__half2*)(g_Ah + rowB + col) = w1;
    }
}

// ============================================================================
extern "C" void kernel_launch(void* const* d_in, const int* in_sizes, int n_in,
                              void* d_out, int out_size)
{
    const float* q  = (const float*)d_in[0];
    const float* k  = (const float*)d_in[1];
    const float* v  = (const float*)d_in[2];
    const int*  mk  = (const int*)  d_in[3];
    const float* Wq = (const float*)d_in[4];
    const float* bq = (const float*)d_in[5];
    const float* Wk = (const float*)d_in[6];
    const float* bk = (const float*)d_in[7];
    const float* Wv = (const float*)d_in[8];
    const float* bv = (const float*)d_in[9];
    const float* Wo = (const float*)d_in[10];
    const float* bo = (const float*)d_in[11];
    float* out = (float*)d_out;

    __half *pAh, *pWh, *pQh, *pKh, *pVh;
    cudaGetSymbolAddress((void**)&pAh, g_Ah);
    cudaGetSymbolAddress((void**)&pWh, g_Wh);
    cudaGetSymbolAddress((void**)&pQh, g_Qh);
    cudaGetSymbolAddress((void**)&pKh, g_Kh);
    cudaGetSymbolAddress((void**)&pVh, g_Vh);

    cudaFuncSetAttribute(gemm_qkv,
                         cudaFuncAttributeMaxDynamicSharedMemorySize, GEMM_SMEM);
    cudaFuncSetAttribute(gemm_out,
                         cudaFuncAttributeMaxDynamicSharedMemorySize, GEMM_SMEM);
    cudaFuncSetAttribute(attn_mma,
                         cudaFuncAttributeMaxDynamicSharedMemorySize, ATT_SMEM);

    dim3 blk(256);

    prep<<<4098, blk>>>(q, k, v, Wq, Wk, Wv, Wo, mk, pAh, pWh);
    gemm_qkv<<<dim3(8, 32, 3), blk, GEMM_SMEM>>>(
        pAh, pWh, bq, bk, bv, pQh, pKh, pVh);
    attn_mma<<<dim3(16, 16, 2), blk, ATT_SMEM>>>();   // writes fp16 ctx -> g_Ah
    gemm_out<<<dim3(8, 32), blk, GEMM_SMEM>>>(pAh, pWh, bo, out);
}

// round 16
// speedup vs baseline: 1.0453x; 1.0453x over previous
#include <cuda_runtime.h>
#include <cuda_fp16.h>
#include <math.h>
#include <stdint.h>

#define B_ 2
#define T_ 2048
#define D_ 1024
#define H_ 16
#define DH_ 64
#define SCALE_ 0.03125f     /* 1/sqrt(1024) exactly */

#define ASTRIDE ((size_t)4096*1024)
#define WSTRIDE ((size_t)1024*1024)

// ============================================================================
// Scratch (static device globals — no allocation in kernel_launch)
// g_Ah slab 0 doubles as the fp16 context buffer (attention epilogue output).
// ============================================================================
__device__ __half g_Ah[3*ASTRIDE];
__device__ __half g_Wh[4*WSTRIDE];
__device__ __half g_Qh[(size_t)B_*H_*T_*DH_];
__device__ __half g_Kh[(size_t)B_*H_*T_*DH_];   // compacted
__device__ __half g_Vh[(size_t)B_*H_*T_*DH_];   // compacted
__device__ int g_pos[B_*T_];
__device__ int g_cnt[B_];

// ============================================================================
// mma.sync / ldmatrix / cp.async helpers (base-target PTX)
// ============================================================================
__device__ __forceinline__ unsigned smem_u32(const void* p) {
    unsigned a;
    asm("{ .reg .u64 t; cvta.to.shared.u64 t, %1; cvt.u32.u64 %0, t; }"
        : "=r"(a) : "l"(p));
    return a;
}
__device__ __forceinline__ void mma_fp(float* c, const unsigned* a, const unsigned* b) {
    asm volatile(
        "mma.sync.aligned.m16n8k16.row.col.f32.f16.f16.f32 "
        "{%0,%1,%2,%3}, {%4,%5,%6,%7}, {%8,%9}, {%0,%1,%2,%3};"
        : "+f"(c[0]), "+f"(c[1]), "+f"(c[2]), "+f"(c[3])
        : "r"(a[0]), "r"(a[1]), "r"(a[2]), "r"(a[3]), "r"(b[0]), "r"(b[1]));
}
__device__ __forceinline__ void ldsm4(unsigned* r, unsigned a) {
    asm volatile("ldmatrix.sync.aligned.m8n8.x4.shared.b16 {%0,%1,%2,%3}, [%4];"
        : "=r"(r[0]), "=r"(r[1]), "=r"(r[2]), "=r"(r[3]) : "r"(a));
}
__device__ __forceinline__ void ldsm4t(unsigned* r, unsigned a) {
    asm volatile("ldmatrix.sync.aligned.m8n8.x4.trans.shared.b16 {%0,%1,%2,%3}, [%4];"
        : "=r"(r[0]), "=r"(r[1]), "=r"(r[2]), "=r"(r[3]) : "r"(a));
}
#define CP16(dst_u32, src_ptr) \
    asm volatile("cp.async.cg.shared.global [%0], [%1], 16;" \
        :: "r"(dst_u32), "l"(src_ptr) : "memory")
#define CP_COMMIT() asm volatile("cp.async.commit_group;" ::: "memory")
#define CP_WAIT1()  asm volatile("cp.async.wait_group 1;"  ::: "memory")

// ============================================================================
// prep: fused conversions + mask scan, MLP=4 per thread (kept from R14).
//   blocks [0, 3072):    A conv (q,k,v), 1024 blocks each, 4 float4/thread
//   blocks [3072, 4096): W conv (4 weights), 256 blocks each
//   blocks [4096, 4098): per-batch mask prefix scan
// ============================================================================
__global__ void __launch_bounds__(256) prep(
    const float* __restrict__ q, const float* __restrict__ k,
    const float* __restrict__ v,
    const float* __restrict__ wq, const float* __restrict__ wk,
    const float* __restrict__ wv, const float* __restrict__ wo,
    const int* __restrict__ mask,
    __half* __restrict__ AhB, __half* __restrict__ WhB)
{
    const int bid = blockIdx.x, tid = threadIdx.x;
    if (bid < 4096) {
        const float* src;
        __half* dst;
        int i0;
        if (bid < 3072) {
            const int z = bid >> 10;
            src = (z == 0) ? q : (z == 1) ? k : v;
            dst = AhB + (size_t)z*ASTRIDE;
            i0 = (bid & 1023) * 1024 + tid;
        } else {
            const int zb = bid - 3072;
            const int z = zb >> 8;
            src = (z == 0) ? wq : (z == 1) ? wk : (z == 2) ? wv : wo;
            dst = WhB + (size_t)z*WSTRIDE;
            i0 = (zb & 255) * 1024 + tid;
        }
        float4 w[4];
        #pragma unroll
        for (int j = 0; j < 4; j++) w[j] = ((const float4*)src)[i0 + j*256];
        #pragma unroll
        for (int j = 0; j < 4; j++) {
            int i = i0 + j*256;
            __half2 a; a.x = __float2half_rn(w[j].x); a.y = __float2half_rn(w[j].y);
            __half2 b; b.x = __float2half_rn(w[j].z); b.y = __float2half_rn(w[j].w);
            ((__half2*)dst)[2*i]   = a;
            ((__half2*)dst)[2*i+1] = b;
        }
    } else {
        __shared__ int ps[256];
        const int b = bid - 4096;
        const int base = b*T_ + tid*8;
        int a[8], s = 0;
        #pragma unroll
        for (int j = 0; j < 8; j++) { a[j] = (mask[base + j] != 0); s += a[j]; }
        ps[tid] = s;
        __syncthreads();
        for (int off = 1; off < 256; off <<= 1) {
            int vsum = ps[tid] + ((tid >= off) ? ps[tid - off] : 0);
            __syncthreads();
            ps[tid] = vsum;
            __syncthreads();
        }
        int run = (tid > 0) ? ps[tid-1] : 0;
        #pragma unroll
        for (int j = 0; j < 8; j++) {
            g_pos[base + j] = a[j] ? run : -1;
            run += a[j];
        }
        if (tid == 255) g_cnt[b] = ps[255];
    }
}

// ============================================================================
// GEMM core: Y = Ah @ Wh + bias   (fp16 single-stream) — unchanged from R13
// ============================================================================
#define GST 35840
#define G_WH_OFF 18432
#define GEMM_SMEM (3*GST)

__device__ __forceinline__ void gemm_core(
    char* gsm,
    const __half* __restrict__ Ah, const __half* __restrict__ Wh,
    const float* __restrict__ bias,
    float* __restrict__ Yf, __half* __restrict__ Yh,
    int emode, int m0, int n0)
{
    const int tid = threadIdx.x, lane = tid & 31, wid = tid >> 5;
    const int wm = wid >> 2, wn = wid & 3;

    float c[4][4][4];
    #pragma unroll
    for (int i = 0; i < 4; i++)
        #pragma unroll
        for (int j = 0; j < 4; j++)
            #pragma unroll
            for (int e = 0; e < 4; e++) c[i][j][e] = 0.f;

    const int l15 = lane & 15, lh8 = (lane >> 4) << 3;
    const unsigned smb = smem_u32(gsm);

    int a_row[4], a_c8[4], w_row[4], w_c8[4];
    #pragma unroll
    for (int t = 0; t < 4; t++) {
        int ch = tid + t*256;
        a_row[t] = ch >> 3;  a_c8[t] = (ch & 7) << 3;
        w_row[t] = ch >> 4;  w_c8[t] = (ch & 15) << 3;
    }

    auto issue = [&](int s, int k0) {
        const unsigned base = smb + s*GST;
        #pragma unroll
        for (int t = 0; t < 4; t++) {
            unsigned aso = base + (unsigned)(a_row[t]*144 + a_c8[t]*2);
            size_t ago = (size_t)(m0 + a_row[t])*1024 + k0 + a_c8[t];
            CP16(aso, Ah + ago);
            unsigned wso = base + G_WH_OFF + (unsigned)(w_row[t]*272 + w_c8[t]*2);
            size_t wgo = (size_t)(k0 + w_row[t])*1024 + n0 + w_c8[t];
            CP16(wso, Wh + wgo);
        }
    };

    issue(0, 0);
    CP_COMMIT();
    issue(1, 64);
    CP_COMMIT();

    for (int kc = 0; kc < 16; kc++) {
        CP_WAIT1();
        __syncthreads();
        if (kc + 2 < 16) issue((kc + 2) % 3, (kc + 2) << 6);
        CP_COMMIT();

        const int buf = kc % 3;
        const __half* sAh = (const __half*)(gsm + buf*GST);
        const __half* sWh = (const __half*)(gsm + buf*GST + G_WH_OFF);

        #pragma unroll
        for (int kk = 0; kk < 64; kk += 16) {
            unsigned a[4][4], bh_[4][2], t4[4];
            #pragma unroll
            for (int mi = 0; mi < 4; mi++)
                ldsm4(a[mi], smem_u32(&sAh[(wm*64 + mi*16 + l15)*72 + kk + lh8]));
            #pragma unroll
            for (int p = 0; p < 2; p++) {
                ldsm4t(t4, smem_u32(&sWh[(kk + l15)*136 + wn*32 + p*16 + lh8]));
                bh_[2*p][0]=t4[0]; bh_[2*p][1]=t4[1];
                bh_[2*p+1][0]=t4[2]; bh_[2*p+1][1]=t4[3];
            }
            #pragma unroll
            for (int mi = 0; mi < 4; mi++)
                #pragma unroll
                for (int ni = 0; ni < 4; ni++) mma_fp(c[mi][ni], a[mi], bh_[ni]);
        }
    }

    // Epilogue
    const int rA = lane >> 2, c2 = (lane & 3) << 1;
    #pragma unroll
    for (int mi = 0; mi < 4; mi++) {
        const int rowA = m0 + wm*64 + mi*16 + rA;
        const int rowB = rowA + 8;
        int pA = rowA & (T_-1), pB = rowB & (T_-1);
        if (emode == 1) { pA = g_pos[rowA]; pB = g_pos[rowB]; }
        #pragma unroll
        for (int ni = 0; ni < 4; ni++) {
            const int col = n0 + wn*32 + ni*8 + c2;
            float2 bb = *(const float2*)(bias + col);
            float v00 = c[mi][ni][0] + bb.x, v01 = c[mi][ni][1] + bb.y;
            float v10 = c[mi][ni][2] + bb.x, v11 = c[mi][ni][3] + bb.y;
            if (emode == 2) {
                float2 w0; w0.x = v00; w0.y = v01;
                float2 w1; w1.x = v10; w1.y = v11;
                *(float2*)(Yf + (size_t)rowA * 1024 + col) = w0;
                *(float2*)(Yf + (size_t)rowB * 1024 + col) = w1;
            } else {
                const int hh = col >> 6, dd = col & 63;
                const int bA = rowA >> 11, bB = rowB >> 11;
                __half2 ph0; ph0.x = __float2half_rn(v00); ph0.y = __float2half_rn(v01);
                __half2 ph1; ph1.x = __float2half_rn(v10); ph1.y = __float2half_rn(v11);
                if (pA >= 0) {
                    size_t oA = (((size_t)(bA*H_ + hh))*T_ + pA)*64 + dd;
                    *(__half2*)(Yh + oA) = ph0;
                }
                if (pB >= 0) {
                    size_t oB = (((size_t)(bB*H_ + hh))*T_ + pB)*64 + dd;
                    *(__half2*)(Yh + oB) = ph1;
                }
            }
        }
    }
}

__global__ void __launch_bounds__(256, 2) gemm_qkv(
    const __half* __restrict__ AhB, const __half* __restrict__ WhB,
    const float* __restrict__ bq, const float* __restrict__ bk,
    const float* __restrict__ bv,
    __half* __restrict__ Qh, __half* __restrict__ Kh, __half* __restrict__ Vh)
{
    extern __shared__ __align__(16) char gsm[];
    const int z = blockIdx.z;
    const float* bias = (z == 0) ? bq : (z == 1) ? bk : bv;
    __half* Yh = (z == 0) ? Qh : (z == 1) ? Kh : Vh;
    gemm_core(gsm, AhB + z*ASTRIDE, WhB + z*WSTRIDE, bias,
              nullptr, Yh, (z == 0) ? 0 : 1,
              blockIdx.y << 7, blockIdx.x << 7);
}

__global__ void __launch_bounds__(256, 2) gemm_out(
    const __half* __restrict__ AhB, const __half* __restrict__ WhB,
    const float* __restrict__ bo, float* __restrict__ out)
{
    extern __shared__ __align__(16) char gsm[];
    gemm_core(gsm, AhB, WhB + 3*WSTRIDE, bo,
              out, nullptr, 2, blockIdx.y << 7, blockIdx.x << 7);
}

// ============================================================================
// Flash attention, warp-per-row-group, 64-key tiles (R13 verbatim — the
// best-measured attention variant).
// ============================================================================
#define ATT_QH   0          /* 128 x 72 half = 18432 */
#define ATT_K    18432      /* 2 bufs x 9216 */
#define ATT_V    36864      /* 2 bufs x 9216 */
#define ATT_PH   55296      /* 128 x 72 half = 18432 */
#define ATT_SMEM 73728

__global__ void __launch_bounds__(256, 2) attn_mma()
{
    extern __shared__ __align__(16) char sm[];
    __half* sQh = (__half*)(sm + ATT_QH);
    __half* sPh = (__half*)(sm + ATT_PH);

    const int tid = threadIdx.x, lane = tid & 31, wid = tid >> 5;
    const int qt0 = blockIdx.x << 7;
    const int hh = blockIdx.y, bb = blockIdx.z;
    const size_t base = ((size_t)(bb*H_ + hh)) * T_ * DH_;
    const int nv = g_cnt[bb];
    const int nt = (nv + 63) >> 6;

    const int r = tid >> 1, cofs = (tid & 1) << 5;
    const int l15 = lane & 15, lh8 = (lane >> 4) << 3;
    const int bn  = (lane & 7) + ((lane >> 4) << 3), bk8 = ((lane >> 3) & 1) << 3;
    const int rA0 = lane >> 2, c2 = (lane & 3) << 1;

    const unsigned smK = smem_u32(sm + ATT_K);
    const unsigned smV = smem_u32(sm + ATT_V);

    int ld_row[2], ld_c8[2];
    #pragma unroll
    for (int t = 0; t < 2; t++) {
        int ch = tid + t*256;
        ld_row[t] = ch >> 3;
        ld_c8[t]  = (ch & 7) << 3;
    }

    // Load Q (persistent)
    {
        const uint4* s1 = (const uint4*)(g_Qh + base + (size_t)(qt0 + r)*64 + cofs);
        uint4* d1 = (uint4*)(sQh + r*72 + cofs);
        d1[0]=s1[0]; d1[1]=s1[1]; d1[2]=s1[2]; d1[3]=s1[3];
    }

    float lrunA = 0.f, lrunB = 0.f;
    float o[8][4];
    #pragma unroll
    for (int g = 0; g < 8; g++)
        #pragma unroll
        for (int e = 0; e < 4; e++) o[g][e] = 0.f;

    // Prologue: tile 0 -> buf 0
    #pragma unroll
    for (int t = 0; t < 2; t++) {
        unsigned so = (unsigned)((ld_row[t]*72 + ld_c8[t]) * 2);
        size_t go = base + (size_t)ld_row[t]*64 + ld_c8[t];
        CP16(smK + so, g_Kh + go);
        CP16(smV + so, g_Vh + go);
    }
    CP_COMMIT();

    const int prow = wid*16;   // this warp's q-row block

    for (int kt = 0; kt < nt; kt++) {
        const int buf = kt & 1;
        if (kt + 1 < nt) {
            const size_t gofs = base + ((size_t)(kt+1) << 6) * 64;
            const unsigned kb = smK + (buf ^ 1) * 9216u;
            const unsigned vb = smV + (buf ^ 1) * 9216u;
            #pragma unroll
            for (int t = 0; t < 2; t++) {
                unsigned so = (unsigned)((ld_row[t]*72 + ld_c8[t]) * 2);
                size_t go = gofs + (size_t)ld_row[t]*64 + ld_c8[t];
                CP16(kb + so, g_Kh + go);
                CP16(vb + so, g_Vh + go);
            }
        }
        CP_COMMIT();
        CP_WAIT1();
        __syncthreads();   // (A) current K/V buffer ready

        __half* sKh = (__half*)(sm + ATT_K + buf*9216);
        __half* sVh = (__half*)(sm + ATT_V + buf*9216);

        // ---- S = Qh·Kh : warp computes 16 rows x 64 keys ----
        float s[8][4];
        #pragma unroll
        for (int g = 0; g < 8; g++)
            #pragma unroll
            for (int e = 0; e < 4; e++) s[g][e] = 0.f;

        #pragma unroll
        for (int kk = 0; kk < 64; kk += 16) {
            unsigned a[4], bf[8][2], t4[4];
            ldsm4(a, smem_u32(&sQh[(prow + l15)*72 + kk + lh8]));
            #pragma unroll
            for (int g = 0; g < 4; g++) {
                ldsm4(t4, smem_u32(&sKh[(g*16 + bn)*72 + kk + bk8]));
                bf[2*g][0]=t4[0]; bf[2*g][1]=t4[1];
                bf[2*g+1][0]=t4[2]; bf[2*g+1][1]=t4[3];
            }
            #pragma unroll
            for (int G = 0; G < 8; G++) mma_fp(s[G], a, bf[G]);
        }

        // ---- warp-local softmax ----
        const int k0g = kt << 6;
        float sumA = 0.f, sumB = 0.f;
        #pragma unroll
        for (int G = 0; G < 8; G++) {
            const int col = G*8 + c2;
            const bool v0 = (k0g + col)     < nv;
            const bool v1 = (k0g + col + 1) < nv;
            float p00 = v0 ? __expf(s[G][0]*SCALE_) : 0.f;
            float p01 = v1 ? __expf(s[G][1]*SCALE_) : 0.f;
            float p10 = v0 ? __expf(s[G][2]*SCALE_) : 0.f;
            float p11 = v1 ? __expf(s[G][3]*SCALE_) : 0.f;
            sumA += p00 + p01;  sumB += p10 + p11;
            __half2 vh0; vh0.x = __float2half_rn(p00); vh0.y = __float2half_rn(p01);
            __half2 vh1; vh1.x = __float2half_rn(p10); vh1.y = __float2half_rn(p11);
            *(__half2*)(sPh + (prow + rA0)*72 + col)     = vh0;
            *(__half2*)(sPh + (prow + rA0 + 8)*72 + col) = vh1;
        }
        sumA += __shfl_xor_sync(0xffffffffu, sumA, 1);
        sumA += __shfl_xor_sync(0xffffffffu, sumA, 2);
        sumB += __shfl_xor_sync(0xffffffffu, sumB, 1);
        sumB += __shfl_xor_sync(0xffffffffu, sumB, 2);
        lrunA += sumA;
        lrunB += sumB;
        __syncwarp();

        // ---- O += Ph·Vh ----
        #pragma unroll
        for (int kk = 0; kk < 64; kk += 16) {
            unsigned pa[4], vf[8][2], t4[4];
            ldsm4(pa, smem_u32(&sPh[(prow + l15)*72 + kk + lh8]));
            #pragma unroll
            for (int g = 0; g < 4; g++) {
                ldsm4t(t4, smem_u32(&sVh[(kk + l15)*72 + g*16 + lh8]));
                vf[2*g][0]=t4[0]; vf[2*g][1]=t4[1];
                vf[2*g+1][0]=t4[2]; vf[2*g+1][1]=t4[3];
            }
            #pragma unroll
            for (int G = 0; G < 8; G++) mma_fp(o[G], pa, vf[G]);
        }
        __syncthreads();   // (C) all warps done with buf before refill
    }

    // ---- normalize + write fp16 ctx into g_Ah slab 0 ----
    const float invA = 1.f / lrunA, invB = 1.f / lrunB;
    const size_t rowA = (size_t)(bb*T_ + qt0 + prow + rA0) * D_ + hh*64;
    const size_t rowB = rowA + (size_t)8 * D_;
    #pragma unroll
    for (int G = 0; G < 8; G++) {
        const int col = G*8 + c2;
        __half2 w0; w0.x = __float2half_rn(o[G][0]*invA);
        w0.y = __float2half_rn(o[G][1]*invA);
        __half2 w1; w1.x = __float2half_rn(o[G][2]*invB);
        w1.y = __float2half_rn(o[G][3]*invB);
        *(__half2*)(g_Ah + rowA + col) = w0;
        *(__half2*)(g_Ah + rowB + col) = w1;
    }
}

// ============================================================================
extern "C" void kernel_launch(void* const* d_in, const int* in_sizes, int n_in,
                              void* d_out, int out_size)
{
    const float* q  = (const float*)d_in[0];
    const float* k  = (const float*)d_in[1];
    const float* v  = (const float*)d_in[2];
    const int*  mk  = (const int*)  d_in[3];
    const float* Wq = (const float*)d_in[4];
    const float* bq = (const float*)d_in[5];
    const float* Wk = (const float*)d_in[6];
    const float* bk = (const float*)d_in[7];
    const float* Wv = (const float*)d_in[8];
    const float* bv = (const float*)d_in[9];
    const float* Wo = (const float*)d_in[10];
    const float* bo = (const float*)d_in[11];
    float* out = (float*)d_out;

    __half *pAh, *pWh, *pQh, *pKh, *pVh;
    cudaGetSymbolAddress((void**)&pAh, g_Ah);
    cudaGetSymbolAddress((void**)&pWh, g_Wh);
    cudaGetSymbolAddress((void**)&pQh, g_Qh);
    cudaGetSymbolAddress((void**)&pKh, g_Kh);
    cudaGetSymbolAddress((void**)&pVh, g_Vh);

    cudaFuncSetAttribute(gemm_qkv,
                         cudaFuncAttributeMaxDynamicSharedMemorySize, GEMM_SMEM);
    cudaFuncSetAttribute(gemm_out,
                         cudaFuncAttributeMaxDynamicSharedMemorySize, GEMM_SMEM);
    cudaFuncSetAttribute(attn_mma,
                         cudaFuncAttributeMaxDynamicSharedMemorySize, ATT_SMEM);

    dim3 blk(256);

    prep<<<4098, blk>>>(q, k, v, Wq, Wk, Wv, Wo, mk, pAh, pWh);
    gemm_qkv<<<dim3(8, 32, 3), blk, GEMM_SMEM>>>(
        pAh, pWh, bq, bk, bv, pQh, pKh, pVh);
    attn_mma<<<dim3(16, 16, 2), blk, ATT_SMEM>>>();   // writes fp16 ctx -> g_Ah
    gemm_out<<<dim3(8, 32), blk, GEMM_SMEM>>>(pAh, pWh, bo, out);
}